// round 15
// baseline (speedup 1.0000x reference)
#include <cuda_runtime.h>
#include <cstdint>

// GAE fused single-pass scan, v15: ALL bulk traffic via TMA (cp.async.bulk),
// bypassing the per-SM LDG outstanding-line queue that capped R8-R14 at
// ~4.1-4.6 TB/s. Block = 512 envs x 8 timesteps; one mbarrier-tracked 64KB
// input fill; compute from smem; bulk stores out. Lookback unchanged.

#define T_STEPS 4096
#define NENV    2048
#define NE2     (NENV / 2)
#define EPB     512                      // envs per block
#define NCOL    (NENV / EPB)             // 4
#define NCHUNK  512
#define CHUNK   8

#define GAMMA_C 0.99f
#define GD_C    (0.99f * 0.95f)

#define ROW_BYTES  (EPB * 4)             // 2048 bytes per (array,row)
#define TILE_BYTES (4 * CHUNK * ROW_BYTES)  // 65536
#define SMEM_BYTES (6 * CHUNK * EPB * 4 + 16)

__device__ float4 g_PS[NCHUNK * NE2];    // (P0,S0,P1,S1) per (chunk, env-pair)
__device__ int    g_flag[NCHUNK * NE2];  // monotone per-run publish counter

// ---------------------------------------------------------------------------
static __device__ __forceinline__ uint32_t s2u(const void* p) {
    uint32_t a;
    asm("{ .reg .u64 t; cvta.to.shared.u64 t, %1; cvt.u32.u64 %0, t; }"
        : "=r"(a) : "l"(p));
    return a;
}
static __device__ __forceinline__ void mbar_init(uint32_t m, uint32_t cnt) {
    asm volatile("mbarrier.init.shared.b64 [%0], %1;" :: "r"(m), "r"(cnt) : "memory");
}
static __device__ __forceinline__ void mbar_expect(uint32_t m, uint32_t bytes) {
    asm volatile("mbarrier.arrive.expect_tx.shared.b64 _, [%0], %1;"
                 :: "r"(m), "r"(bytes) : "memory");
}
static __device__ __forceinline__ void bulk_g2s(uint32_t sdst, const void* gsrc,
                                                uint32_t bytes, uint32_t m) {
    asm volatile(
        "cp.async.bulk.shared::cta.global.mbarrier::complete_tx::bytes [%0], [%1], %2, [%3];"
        :: "r"(sdst), "l"(gsrc), "r"(bytes), "r"(m) : "memory");
}
static __device__ __forceinline__ void bulk_s2g(void* gdst, uint32_t ssrc, uint32_t bytes) {
    asm volatile("cp.async.bulk.global.shared::cta.bulk_group [%0], [%1], %2;"
                 :: "l"(gdst), "r"(ssrc), "r"(bytes) : "memory");
}
static __device__ __forceinline__ void mbar_wait(uint32_t m, uint32_t parity) {
    asm volatile(
        "{\n\t.reg .pred P1;\n"
        "W%=:\n\tmbarrier.try_wait.parity.acquire.cta.shared::cta.b64 P1, [%0], %1, 0x989680;\n\t"
        "@P1 bra D%=;\n\tbra W%=;\n"
        "D%=:\n\t}"
        :: "r"(m), "r"(parity) : "memory");
}

// ---------------------------------------------------------------------------
__global__ void __launch_bounds__(256) gae_fused(
    const float* __restrict__ rewards,
    const float* __restrict__ values,
    const float* __restrict__ next_values,
    const int*   __restrict__ next_dones,
    float* __restrict__ adv,
    float* __restrict__ ret)
{
    extern __shared__ __align__(16) char smem[];
    float* sR  = (float*)smem;                 // [CHUNK][EPB] 16KB
    float* sV  = sR  + CHUNK * EPB;
    float* sNV = sV  + CHUNK * EPB;
    int*   sD  = (int*)(sNV + CHUNK * EPB);
    float* sA  = (float*)(sD + CHUNK * EPB);   // adv staging
    float* sRt = sA  + CHUNK * EPB;            // ret staging
    uint64_t* mbarp = (uint64_t*)(sRt + CHUNK * EPB);
    const uint32_t mb = s2u(mbarp);

    const int tid = threadIdx.x;
    const int colBase = blockIdx.x * EPB;                  // env offset
    const int c = (NCHUNK - 1) - blockIdx.y;               // latest chunk = bid 0
    const int o = c * NE2 + (colBase / 2 + tid);           // env-pair slot

    // Self-incrementing flag protocol (slot written once per run, owner-only).
    const int f0 = ((volatile int*)g_flag)[o];
    const int fpub = f0 + 1;

    // ---- TMA input fill: 32 bulk copies, one mbarrier, one wait ----
    if (tid == 0) mbar_init(mb, 1);
    __syncthreads();
    if (tid == 0) {
        mbar_expect(mb, TILE_BYTES);
        #pragma unroll
        for (int j = 0; j < CHUNK; j++) {
            const size_t goff = (size_t)(c * CHUNK + j) * NENV + colBase;
            bulk_g2s(s2u(sR  + j * EPB), rewards     + goff, ROW_BYTES, mb);
            bulk_g2s(s2u(sV  + j * EPB), values      + goff, ROW_BYTES, mb);
            bulk_g2s(s2u(sNV + j * EPB), next_values + goff, ROW_BYTES, mb);
            bulk_g2s(s2u(sD  + j * EPB), next_dones  + goff, ROW_BYTES, mb);
        }
    }
    mbar_wait(mb, 0);

    // ---- Phase A: backward scan from smem (2 envs/thread) ----
    const int le = 2 * tid;
    float g0 = 0.f, g1 = 0.f, p0 = 1.f, p1 = 1.f;
    unsigned int b0 = 0u, b1 = 0u;
    bool a0 = true, a1 = true;

    #pragma unroll
    for (int t = 0; t < CHUNK; t++) {                      // t=0 is LAST timestep
        const int j = CHUNK - 1 - t;
        const float2 r  = *(const float2*)&sR [j * EPB + le];
        const float2 v  = *(const float2*)&sV [j * EPB + le];
        const float2 nv = *(const float2*)&sNV[j * EPB + le];
        const int2   d  = *(const int2*)  &sD [j * EPB + le];

        const float nd0 = d.x ? 0.f : 1.f;
        const float nd1 = d.y ? 0.f : 1.f;
        g0 = (r.x + GAMMA_C * nv.x * nd0 - v.x) + GD_C * nd0 * g0;
        g1 = (r.y + GAMMA_C * nv.y * nd1 - v.y) + GD_C * nd1 * g1;
        p0 *= GD_C * nd0;
        p1 *= GD_C * nd1;
        a0 = a0 && (d.x == 0);
        a1 = a1 && (d.y == 0);
        if (a0) b0 |= (1u << t);
        if (a1) b1 |= (1u << t);
        *(float2*)&sA [j * EPB + le] = make_float2(g0, g1);           // provisional adv
        *(float2*)&sRt[j * EPB + le] = make_float2(g0 + v.x, g1 + v.y); // provisional ret
    }

    // ---- Publish aggregate ----
    g_PS[o] = make_float4(p0, g0, p1, g1);
    __threadfence();
    ((volatile int*)g_flag)[o] = fpub;

    // ---- Phase B: compose G (walk terminates ~1 hop; chunk all-alive w.p. 2^-8)
    float G0 = 0.f, G1 = 0.f;
    if (c < NCHUNK - 1) {
        float aP0 = 1.f, aS0 = 0.f, aP1 = 1.f, aS1 = 0.f;
        int w = o + NE2;
        const int wend = NCHUNK * NE2;
        while (w < wend && (aP0 > 1e-12f || aP1 > 1e-12f)) {
            while (((volatile int*)g_flag)[w] != fpub) __nanosleep(40);
            __threadfence();                               // acquire
            const float4 ps = __ldcg(&g_PS[w]);
            aS0 += aP0 * ps.y;  aP0 *= ps.x;
            aS1 += aP1 * ps.w;  aP1 *= ps.z;
            w += NE2;
        }
        G0 = aS0;
        G1 = aS1;
    }

    // ---- Phase C: sparse fixup in smem (bits is a prefix mask, E[len]~1) ----
    const int kmax = max(__popc(b0), __popc(b1));
    float pw = GD_C;
    for (int t = 0; t < kmax; t++) {
        const int j = CHUNK - 1 - t;
        const float fx0 = ((b0 >> t) & 1u) ? pw * G0 : 0.f;
        const float fx1 = ((b1 >> t) & 1u) ? pw * G1 : 0.f;
        float2 a  = *(float2*)&sA [j * EPB + le];
        float2 rr = *(float2*)&sRt[j * EPB + le];
        a.x += fx0;  a.y += fx1;
        rr.x += fx0; rr.y += fx1;
        *(float2*)&sA [j * EPB + le] = a;
        *(float2*)&sRt[j * EPB + le] = rr;
        pw *= GD_C;
    }

    // ---- TMA bulk store out ----
    __syncthreads();
    asm volatile("fence.proxy.async.shared::cta;" ::: "memory");
    if (tid == 0) {
        #pragma unroll
        for (int j = 0; j < CHUNK; j++) {
            const size_t goff = (size_t)(c * CHUNK + j) * NENV + colBase;
            bulk_s2g(adv + goff, s2u(sA  + j * EPB), ROW_BYTES);
            bulk_s2g(ret + goff, s2u(sRt + j * EPB), ROW_BYTES);
        }
        asm volatile("cp.async.bulk.commit_group;" ::: "memory");
        asm volatile("cp.async.bulk.wait_group 0;" ::: "memory");
    }
}

// ---------------------------------------------------------------------------
extern "C" void kernel_launch(void* const* d_in, const int* in_sizes, int n_in,
                              void* d_out, int out_size)
{
    const float* rewards     = (const float*)d_in[0];
    const float* values      = (const float*)d_in[1];
    const float* next_values = (const float*)d_in[2];
    const int*   next_dones  = (const int*)d_in[3];

    float* adv = (float*)d_out;
    float* ret = (float*)d_out + (size_t)T_STEPS * NENV;

    cudaFuncSetAttribute(gae_fused, cudaFuncAttributeMaxDynamicSharedMemorySize,
                         SMEM_BYTES);

    dim3 block(256);
    dim3 grid(NCOL, NCHUNK);   // (4, 512) = 2048 blocks
    gae_fused<<<grid, block, SMEM_BYTES>>>(rewards, values, next_values,
                                           next_dones, adv, ret);
}

// round 16
// speedup vs baseline: 1.3214x; 1.3214x over previous
#include <cuda_runtime.h>

// GAE fused single-pass scan, v16 = v11 resubmitted (wall-gap noise retest).
// v11 holds the best measured kernel time (37.95us); its 45.8us wall had a
// 7.9us kernel->wall gap vs 1.1us for structurally identical launches in
// other rounds -> re-bench per rigor.md before drawing conclusions.
//
// - Single kernel launch: self-incrementing flag protocol (each slot is
//   written once per run by its owner only; owner reads its own stale value
//   f0, publishes f0+1, waits on flag[w]==f0+1). No reset/epoch kernel.
// - S and V both in smem (32KB/block): phase C touches no global reads.
// - All inputs streamed once with __ldcs; outputs streamed once with __stcs.
//   DRAM traffic = compulsory 134MB R + 67MB W.

#define T_STEPS 4096
#define NENV    2048
#define NCHUNK  256
#define CHUNK   16

#define GAMMA_C 0.99f
#define GD_C    (0.99f * 0.95f)

__device__ float2 g_PS[NCHUNK * NENV];    // (P, S) aggregate per (chunk, env)
__device__ int    g_flag[NCHUNK * NENV];  // monotone per-run publish counter

// ---------------------------------------------------------------------------
__global__ void __launch_bounds__(256) gae_fused(
    const float* __restrict__ rewards,
    const float* __restrict__ values,
    const float* __restrict__ next_values,
    const int*   __restrict__ next_dones,
    float* __restrict__ adv,
    float* __restrict__ ret)
{
    __shared__ float sS[CHUNK * 256];                      // 16KB: local scan value
    __shared__ float sV[CHUNK * 256];                      // 16KB: values

    const int tid = threadIdx.x;
    const int e = blockIdx.x * blockDim.x + tid;           // env
    const int c = (NCHUNK - 1) - blockIdx.y;               // latest chunk = bid 0
    const int base = ((c + 1) * CHUNK - 1) * NENV + e;     // last timestep of chunk
    const int o = c * NENV + e;

    // Own slot's pre-publish value: every slot ended the previous run at the
    // same count (each is published exactly once per run, only by its owner).
    const int f0 = ((volatile int*)g_flag)[o];
    const int fpub = f0 + 1;

    // ---- Phase A: local backward scan; S,V -> smem; inputs streamed once ----
    float g = 0.0f, p = 1.0f;
    unsigned int bits = 0u;
    bool alive = true;

    #pragma unroll
    for (int t = 0; t < CHUNK; t++) {                      // t=0 is LAST timestep
        const int idx = base - t * NENV;
        const int   dd = __ldcs(&next_dones[idx]);
        const float rr = __ldcs(&rewards[idx]);
        const float nv = __ldcs(&next_values[idx]);
        const float vv = __ldcs(&values[idx]);

        const float nd = dd ? 0.0f : 1.0f;
        g = (rr + GAMMA_C * nv * nd - vv) + GD_C * nd * g;
        p *= GD_C * nd;
        alive = alive && (dd == 0);
        if (alive) bits |= (1u << t);
        sS[t * 256 + tid] = g;
        sV[t * 256 + tid] = vv;
    }

    // ---- Publish aggregate ----
    g_PS[o] = make_float2(p, g);
    __threadfence();
    ((volatile int*)g_flag)[o] = fpub;

    // ---- Phase B: compose G from later chunks' aggregates.
    // dones ~ Bernoulli(0.5): a 16-step chunk is all-alive w.p. 2^-16, so
    // accP hits 0 after ~1 hop; walk is latency-trivial.
    float G = 0.0f;
    if (c < NCHUNK - 1) {
        float accP = 1.0f, accS = 0.0f;
        int w = o + NENV;                                  // next-later chunk, same env
        const int wend = NCHUNK * NENV;
        while (w < wend && accP > 1e-12f) {
            while (((volatile int*)g_flag)[w] != fpub) __nanosleep(40);
            __threadfence();                               // acquire
            const float2 ps = __ldcg(&g_PS[w]);
            accS += accP * ps.y;
            accP *= ps.x;
            w += NENV;
        }
        G = accS;
    }

    // ---- Phase C: fixup from smem only; stream outputs exactly once ----
    float pw = GD_C;
    #pragma unroll
    for (int t = 0; t < CHUNK; t++) {
        const int idx = base - t * NENV;
        const float fix = ((bits >> t) & 1u) ? pw * G : 0.0f;
        const float a = sS[t * 256 + tid] + fix;
        __stcs(&adv[idx], a);
        __stcs(&ret[idx], a + sV[t * 256 + tid]);
        pw *= GD_C;
    }
}

// ---------------------------------------------------------------------------
extern "C" void kernel_launch(void* const* d_in, const int* in_sizes, int n_in,
                              void* d_out, int out_size)
{
    const float* rewards     = (const float*)d_in[0];
    const float* values      = (const float*)d_in[1];
    const float* next_values = (const float*)d_in[2];
    const int*   next_dones  = (const int*)d_in[3];

    float* adv = (float*)d_out;
    float* ret = (float*)d_out + (size_t)T_STEPS * NENV;

    dim3 block(256);
    dim3 grid(NENV / 256, NCHUNK);   // (8, 256) = 2048 blocks
    gae_fused<<<grid, block>>>(rewards, values, next_values, next_dones, adv, ret);
}